// round 6
// baseline (speedup 1.0000x reference)
#include <cuda_runtime.h>
#include <cuda_bf16.h>
#include <math.h>
#include <stdint.h>

#define NB 128
#define NT 2048
#define NH 200
#define NH4 800
#define NSTEP 5

// ---- scratch ----
__device__ float g_qproj[NB * NH];
__device__ float g_hpre[NB * NH4];
__device__ float g_scores[NB * NT];
__device__ float g_context[NB * NH];
__device__ float g_gc[NB * NH4];

__device__ __forceinline__ float sigm(float x) { return 1.f / (1.f + expf(-x)); }

__device__ __forceinline__ float tanh_mufu(float x) {
    float m = x * 2.8853900817779268f;   // 2*log2(e)
    float e; asm("ex2.approx.ftz.f32 %0, %1;" : "=f"(e) : "f"(m));
    float d = 1.f + e;
    float rc; asm("rcp.approx.ftz.f32 %0, %1;" : "=f"(rc) : "f"(d));
    return fmaf(-2.f, rc, 1.f);
}

__device__ __forceinline__ uint32_t pack_bf2(float lo, float hi) {
    uint32_t r;
    asm("cvt.rn.bf16x2.f32 %0, %1, %2;" : "=r"(r) : "f"(hi), "f"(lo));
    return r;
}
__device__ __forceinline__ float warp_sum(float s) {
    #pragma unroll
    for (int o = 16; o; o >>= 1) s += __shfl_xor_sync(0xffffffffu, s, o);
    return s;
}
__device__ __forceinline__ uint32_t s2u(const void* p) {
    return (uint32_t)__cvta_generic_to_shared(p);
}

// no-op kernel: keeps ncu's captured launch index on k_scores
__global__ void k_nop() {}

// ============================================================================
// K1: warp-per-output gemv: q_proj (Wa) + h_pre (W_hh).  grid(5, NB)
// ============================================================================
__global__ void k_pre(const float* __restrict__ h0, const float* __restrict__ Wa,
                      const float* __restrict__ ba, const float* __restrict__ Whh,
                      const float* __restrict__ bhh) {
    const int b = blockIdx.y, oc = blockIdx.x, tid = threadIdx.x;
    const int w = tid >> 5, l = tid & 31;
    __shared__ float hs[NH];
    if (tid < NH) hs[tid] = h0[b * NH + tid];
    __syncthreads();
    #pragma unroll 1
    for (int i = 0; i < 25; i++) {
        int o = oc * 200 + w * 25 + i;
        const float* row;
        if (o < NH) row = Wa + o * NH;
        else        row = Whh + (o - NH) * NH;
        float s = 0.f;
        #pragma unroll
        for (int k = l; k < NH; k += 32) s = fmaf(hs[k], row[k], s);
        s = warp_sum(s);
        if (l == 0) {
            if (o < NH) g_qproj[b * NH + o] = s + ba[o];
            else        g_hpre[b * NH4 + (o - NH)] = s + bhh[o - NH];
        }
    }
}

// ============================================================================
// K2: scores GEMM with Ua as the A-operand, RESIDENT IN REGISTERS.
//   13 compute warps each own a fixed m16 slice of Ua (a[13][4], loaded once).
//   enc tokens are the B/n dimension: per tile only 13 ldmatrix.x4 B loads
//   feed 104 MMAs per warp.  Warps 13-15 stage the next enc tile (dbl-buf).
//   Epilogue: tanh(D + q[m]) . va[m] summed over m via shfl + srow slabs.
// ============================================================================
#define NCTA 148
#define TOK 64
#define ASTR 216                 // bf16 stride per smem row
#define AW 108                   // u32 per row
#define TILE_U32 (TOK * AW)      // 6912
#define NTILES (NB * 32)
#define SMEM_SC ((2 * TILE_U32 + 13 * 64) * 4 + 64)

__device__ __forceinline__ uint32_t ldua(const float* __restrict__ Ua, int r, int k) {
    float x = 0.f, y = 0.f;
    if (r < NH) {
        if (k < NH)     x = Ua[r * NH + k];
        if (k + 1 < NH) y = Ua[r * NH + k + 1];
    }
    return pack_bf2(x, y);
}

__device__ __forceinline__ void stage_enc(uint32_t* __restrict__ dst,
                                          const float* __restrict__ eb,
                                          int sid, int nthr) {
    #pragma unroll 1
    for (int i = sid; i < TOK * 104; i += nthr) {
        int r = i / 104, p = i - r * 104;
        uint32_t v = 0;
        if (p < 100) {
            float2 f = *(const float2*)(eb + r * NH + 2 * p);
            v = pack_bf2(f.x, f.y);
        }
        dst[r * AW + p] = v;
    }
}

__global__ __launch_bounds__(512, 1) void k_scores(
    const float* __restrict__ enc, const float* __restrict__ Ua,
    const float* __restrict__ bua, const float* __restrict__ Va,
    const float* __restrict__ bva) {
    extern __shared__ uint32_t sm32[];
    uint32_t* As0 = sm32;
    uint32_t* As1 = sm32 + TILE_U32;
    float* srow = (float*)(sm32 + 2 * TILE_U32);   // [13][64]

    const int tid = threadIdx.x, l = tid & 31, wid = tid >> 5;
    const int bid = blockIdx.x;
    const float bv0 = bva[0];
    const int r0 = 16 * wid + (l >> 2);    // this warp's Ua row (compute warps)
    const int c0 = 2 * (l & 3);

    // ---- A fragments: Ua slice, loaded ONCE, lives in registers forever ----
    uint32_t a[13][4];
    float vlo = 0.f, vhi = 0.f;
    if (wid < 13) {
        #pragma unroll
        for (int kt = 0; kt < 13; kt++) {
            int k0 = 16 * kt + c0;
            a[kt][0] = ldua(Ua, r0,     k0);
            a[kt][1] = ldua(Ua, r0 + 8, k0);
            a[kt][2] = ldua(Ua, r0,     k0 + 8);
            a[kt][3] = ldua(Ua, r0 + 8, k0 + 8);
        }
        vlo = (r0 < NH) ? Va[r0] : 0.f;
        vhi = (r0 + 8 < NH) ? Va[r0 + 8] : 0.f;
    }

    const int ntile = (NTILES - bid + NCTA - 1) / NCTA;
    stage_enc(As0, enc + ((size_t)(bid >> 5) * NT + (bid & 31) * TOK) * NH, tid, 512);
    __syncthreads();

    const uint32_t brow = (uint32_t)((l & 7) + ((l >> 4) << 3));
    const uint32_t bko = (uint32_t)(((l >> 3) & 1) * 16);

    #pragma unroll 1
    for (int it = 0; it < ntile; it++) {
        const int gt = bid + it * NCTA;
        const int b = gt >> 5;
        uint32_t* Ac = (it & 1) ? As1 : As0;

        if (wid >= 13) {
            // dedicated stagers: fill the other buffer with the next tile
            if (it + 1 < ntile) {
                int gn = bid + (it + 1) * NCTA;
                stage_enc((it & 1) ? As0 : As1,
                          enc + ((size_t)(gn >> 5) * NT + (gn & 31) * TOK) * NH,
                          tid - 13 * 32, 96);
            }
        } else {
            const float qlo = (r0 < NH) ? (g_qproj[b * NH + r0] + bua[r0]) : 0.f;
            const float qhi = (r0 + 8 < NH) ? (g_qproj[b * NH + r0 + 8] + bua[r0 + 8]) : 0.f;
            float acc[8][4];
            #pragma unroll
            for (int n = 0; n < 8; n++)
                #pragma unroll
                for (int c = 0; c < 4; c++) acc[n][c] = 0.f;

            const uint32_t bb0 = s2u(Ac) + brow * (ASTR * 2) + bko;
            #pragma unroll
            for (int kt = 0; kt < 13; kt++) {
                #pragma unroll
                for (int ntp = 0; ntp < 4; ntp++) {
                    uint32_t b0, b1, b2, b3;
                    asm volatile("ldmatrix.sync.aligned.m8n8.x4.shared.b16 {%0,%1,%2,%3}, [%4];"
                        : "=r"(b0), "=r"(b1), "=r"(b2), "=r"(b3)
                        : "r"(bb0 + (uint32_t)(ntp * 16 * ASTR * 2 + kt * 32)));
                    asm volatile("mma.sync.aligned.m16n8k16.row.col.f32.bf16.bf16.f32 "
                        "{%0,%1,%2,%3},{%4,%5,%6,%7},{%8,%9},{%0,%1,%2,%3};"
                        : "+f"(acc[2*ntp][0]), "+f"(acc[2*ntp][1]),
                          "+f"(acc[2*ntp][2]), "+f"(acc[2*ntp][3])
                        : "r"(a[kt][0]), "r"(a[kt][1]), "r"(a[kt][2]), "r"(a[kt][3]),
                          "r"(b0), "r"(b1));
                    asm volatile("mma.sync.aligned.m16n8k16.row.col.f32.bf16.bf16.f32 "
                        "{%0,%1,%2,%3},{%4,%5,%6,%7},{%8,%9},{%0,%1,%2,%3};"
                        : "+f"(acc[2*ntp+1][0]), "+f"(acc[2*ntp+1][1]),
                          "+f"(acc[2*ntp+1][2]), "+f"(acc[2*ntp+1][3])
                        : "r"(a[kt][0]), "r"(a[kt][1]), "r"(a[kt][2]), "r"(a[kt][3]),
                          "r"(b2), "r"(b3));
                }
            }
            // epilogue: tanh + va, reduce over this warp's 16 m-rows
            #pragma unroll
            for (int nt = 0; nt < 8; nt++) {
                float t0 = vlo * tanh_mufu(acc[nt][0] + qlo)
                         + vhi * tanh_mufu(acc[nt][2] + qhi);
                float t1 = vlo * tanh_mufu(acc[nt][1] + qlo)
                         + vhi * tanh_mufu(acc[nt][3] + qhi);
                t0 += __shfl_xor_sync(0xffffffffu, t0, 4);
                t0 += __shfl_xor_sync(0xffffffffu, t0, 8);
                t0 += __shfl_xor_sync(0xffffffffu, t0, 16);
                t1 += __shfl_xor_sync(0xffffffffu, t1, 4);
                t1 += __shfl_xor_sync(0xffffffffu, t1, 8);
                t1 += __shfl_xor_sync(0xffffffffu, t1, 16);
                if (l < 4) {
                    srow[wid * 64 + nt * 8 + 2 * l]     = t0;
                    srow[wid * 64 + nt * 8 + 2 * l + 1] = t1;
                }
            }
        }
        __syncthreads();
        if (tid < 64) {
            float s = bv0;
            #pragma unroll
            for (int w = 0; w < 13; w++) s += srow[w * 64 + tid];
            g_scores[(size_t)b * NT + (gt & 31) * TOK + tid] = s;
        }
        __syncthreads();
    }
}

// ============================================================================
// K3: softmax over T + context.
// ============================================================================
__global__ __launch_bounds__(1024) void k_softctx(const float* __restrict__ enc) {
    const int b = blockIdx.x, tid = threadIdx.x;
    __shared__ float at[NT];
    __shared__ float red[1024];
    __shared__ float part[4][NH];

    float m = -1e30f;
    #pragma unroll
    for (int t = tid; t < NT; t += 1024) {
        float s = g_scores[(size_t)b * NT + t];
        at[t] = s;
        m = fmaxf(m, s);
    }
    red[tid] = m; __syncthreads();
    for (int o = 512; o; o >>= 1) {
        if (tid < o) red[tid] = fmaxf(red[tid], red[tid + o]);
        __syncthreads();
    }
    m = red[0]; __syncthreads();

    float lsum = 0.f;
    #pragma unroll
    for (int t = tid; t < NT; t += 1024) {
        float e = expf(at[t] - m);
        at[t] = e;
        lsum += e;
    }
    red[tid] = lsum; __syncthreads();
    for (int o = 512; o; o >>= 1) {
        if (tid < o) red[tid] += red[tid + o];
        __syncthreads();
    }
    const float inv = 1.f / red[0];
    __syncthreads();

    const int p = tid >> 8, hh = tid & 255;
    if (hh < NH) {
        const float* e = enc + (size_t)b * NT * NH + (size_t)p * 512 * NH + hh;
        const float* atp = at + p * 512;
        float a = 0.f;
        #pragma unroll 8
        for (int t = 0; t < 512; t++) a = fmaf(atp[t], e[(size_t)t * NH], a);
        part[p][hh] = a;
    }
    __syncthreads();
    if (tid < NH)
        g_context[b * NH + tid] =
            (part[0][tid] + part[1][tid] + part[2][tid] + part[3][tid]) * inv;
}

// ============================================================================
// K4: gates_const[b,j] = b_ih[j] + h_pre[b,j] + ctx . W_ih[j,1:]   grid(4,NB)
// ============================================================================
__global__ void k_gates(const float* __restrict__ Wih, const float* __restrict__ bih) {
    const int b = blockIdx.y, jc = blockIdx.x, tid = threadIdx.x;
    const int w = tid >> 5, l = tid & 31;
    __shared__ float ctx[NH];
    if (tid < NH) ctx[tid] = g_context[b * NH + tid];
    __syncthreads();
    #pragma unroll 1
    for (int i = 0; i < 25; i++) {
        int j = jc * 200 + w * 25 + i;
        const float* row = Wih + (size_t)j * (NH + 1) + 1;
        float s = 0.f;
        #pragma unroll
        for (int k = l; k < NH; k += 32) s = fmaf(ctx[k], row[k], s);
        s = warp_sum(s);
        if (l == 0) g_gc[b * NH4 + j] = s + bih[j] + g_hpre[b * NH4 + j];
    }
}

// ============================================================================
// K5: 5-step decode.
// ============================================================================
#define SMEM_DEC ((20000 + 5000 + 64 + 128 + 64 + NH4 + NH4 + NH + NH + 128 + 64 + 8) * 4)
__global__ __launch_bounds__(256) void k_decode(
    const float* __restrict__ x_in, const float* __restrict__ c0,
    const float* __restrict__ Wih,
    const float* __restrict__ W1, const float* __restrict__ b1,
    const float* __restrict__ W2, const float* __restrict__ b2,
    const float* __restrict__ W3, const float* __restrict__ b3,
    float* __restrict__ out) {
    extern __shared__ float sd[];
    float* W1s = sd;
    float* W2s = W1s + 20000;
    float* W3s = W2s + 5000;
    float* b1s = W3s + 64;
    float* b2s = b1s + 128;
    float* gc  = b2s + 64;
    float* w0  = gc + NH4;
    float* c0s = w0 + NH4;
    float* buf0 = c0s + NH;
    float* buf1 = buf0 + NH;
    float* buf2 = buf1 + 128;
    float* xcur = buf2 + 64;

    const int b = blockIdx.x, tid = threadIdx.x;
    const int w = tid >> 5, l = tid & 31;

    for (int i = tid; i < 20000; i += 256) W1s[i] = W1[i];
    for (int i = tid; i < 5000; i += 256) W2s[i] = W2[i];
    if (tid < 50) { W3s[tid] = W3[tid]; b2s[tid] = b2[tid]; }
    if (tid < 100) b1s[tid] = b1[tid];
    for (int i = tid; i < NH4; i += 256) {
        gc[i] = g_gc[b * NH4 + i];
        w0[i] = Wih[(size_t)i * (NH + 1)];
    }
    if (tid < NH) c0s[tid] = c0[b * NH + tid];
    if (tid == 0) xcur[0] = x_in[b];
    __syncthreads();

    const float b3v = b3[0];
    for (int st = 0; st < NSTEP; st++) {
        const float xv = xcur[0];
        if (tid < NH) {
            float gi = fmaf(xv, w0[tid], gc[tid]);
            float gf = fmaf(xv, w0[NH + tid], gc[NH + tid]);
            float gg = fmaf(xv, w0[2 * NH + tid], gc[2 * NH + tid]);
            float go = fmaf(xv, w0[3 * NH + tid], gc[3 * NH + tid]);
            float c  = sigm(gf) * c0s[tid] + sigm(gi) * tanhf(gg);
            buf0[tid] = fmaxf(sigm(go) * tanhf(c), 0.f);
        }
        __syncthreads();
        #pragma unroll 1
        for (int i = 0; i < 13; i++) {
            int j = w + 8 * i; int jj = min(j, 99);
            float s = 0.f;
            #pragma unroll
            for (int k = l; k < NH; k += 32) s = fmaf(W1s[jj * NH + k], buf0[k], s);
            s = warp_sum(s);
            if (l == 0 && j < 100) buf1[j] = fmaxf(s + b1s[j], 0.f);
        }
        __syncthreads();
        #pragma unroll 1
        for (int i = 0; i < 7; i++) {
            int j = w + 8 * i; int jj = min(j, 49);
            float s = 0.f;
            #pragma unroll
            for (int k = l; k < 100; k += 32) s = fmaf(W2s[jj * 100 + k], buf1[k], s);
            s = warp_sum(s);
            if (l == 0 && j < 50) buf2[j] = fmaxf(s + b2s[j], 0.f);
        }
        __syncthreads();
        if (w == 0) {
            float s = (l < 50) ? W3s[l] * buf2[l] : 0.f;
            if (l < 18) s = fmaf(W3s[l + 32], buf2[l + 32], s);
            s = warp_sum(s);
            if (l == 0) {
                float y = s + b3v;
                out[b * NSTEP + st] = y;
                xcur[0] = y;
            }
        }
        __syncthreads();
    }
}

// ============================================================================
extern "C" void kernel_launch(void* const* d_in, const int* in_sizes, int n_in,
                              void* d_out, int out_size) {
    const float* x   = (const float*)d_in[0];
    const float* h0  = (const float*)d_in[1];
    const float* c0  = (const float*)d_in[2];
    const float* enc = (const float*)d_in[3];
    const float* Wa  = (const float*)d_in[4];
    const float* ba  = (const float*)d_in[5];
    const float* Ua  = (const float*)d_in[6];
    const float* bua = (const float*)d_in[7];
    const float* Va  = (const float*)d_in[8];
    const float* bva = (const float*)d_in[9];
    const float* Wih = (const float*)d_in[10];
    const float* Whh = (const float*)d_in[11];
    const float* bih = (const float*)d_in[12];
    const float* bhh = (const float*)d_in[13];
    const float* W1  = (const float*)d_in[14];
    const float* b1  = (const float*)d_in[15];
    const float* W2  = (const float*)d_in[16];
    const float* b2  = (const float*)d_in[17];
    const float* W3  = (const float*)d_in[18];
    const float* b3  = (const float*)d_in[19];
    float* out = (float*)d_out;

    cudaFuncSetAttribute(k_scores, cudaFuncAttributeMaxDynamicSharedMemorySize,
                         (int)SMEM_SC);
    cudaFuncSetAttribute(k_decode, cudaFuncAttributeMaxDynamicSharedMemorySize,
                         (int)SMEM_DEC);

    k_pre<<<dim3(5, NB), 256>>>(h0, Wa, ba, Whh, bhh);
    k_nop<<<1, 32>>>();
    k_nop<<<1, 32>>>();
    k_scores<<<NCTA, 512, SMEM_SC>>>(enc, Ua, bua, Va, bva);   // in-call index 3 -> profiled
    k_softctx<<<NB, 1024>>>(enc);
    k_gates<<<dim3(4, NB), 256>>>(Wih, bih);
    k_decode<<<NB, 256, SMEM_DEC>>>(x, c0, Wih, W1, b1, W2, b2, W3, b3, out);
}

// round 7
// speedup vs baseline: 2.4795x; 2.4795x over previous
#include <cuda_runtime.h>
#include <cuda_bf16.h>
#include <math.h>
#include <stdint.h>

#define NB 128
#define NT 2048
#define NH 200
#define NH4 800
#define NSTEP 5

// ---- scratch ----
__device__ float g_qproj[NB * NH];
__device__ float g_hpre[NB * NH4];
__device__ float g_scores[NB * NT];
__device__ float g_context[NB * NH];
__device__ float g_gc[NB * NH4];

__device__ __forceinline__ float sigm(float x) { return 1.f / (1.f + expf(-x)); }

__device__ __forceinline__ float tanh_mufu(float x) {
    float m = x * 2.8853900817779268f;   // 2*log2(e)
    float e; asm("ex2.approx.ftz.f32 %0, %1;" : "=f"(e) : "f"(m));
    float d = 1.f + e;
    float rc; asm("rcp.approx.ftz.f32 %0, %1;" : "=f"(rc) : "f"(d));
    return fmaf(-2.f, rc, 1.f);
}

__device__ __forceinline__ uint32_t pack_bf2(float lo, float hi) {
    uint32_t r;
    asm("cvt.rn.bf16x2.f32 %0, %1, %2;" : "=r"(r) : "f"(hi), "f"(lo));
    return r;
}
__device__ __forceinline__ float warp_sum(float s) {
    #pragma unroll
    for (int o = 16; o; o >>= 1) s += __shfl_xor_sync(0xffffffffu, s, o);
    return s;
}
__device__ __forceinline__ uint32_t s2u(const void* p) {
    return (uint32_t)__cvta_generic_to_shared(p);
}

// no-op kernel: keeps ncu's captured launch index on k_scores
__global__ void k_nop() {}

// ============================================================================
// K1: warp-per-output gemv: q_proj (Wa) + h_pre (W_hh).  grid(5, NB)
// ============================================================================
__global__ void k_pre(const float* __restrict__ h0, const float* __restrict__ Wa,
                      const float* __restrict__ ba, const float* __restrict__ Whh,
                      const float* __restrict__ bhh) {
    const int b = blockIdx.y, oc = blockIdx.x, tid = threadIdx.x;
    const int w = tid >> 5, l = tid & 31;
    __shared__ float hs[NH];
    if (tid < NH) hs[tid] = h0[b * NH + tid];
    __syncthreads();
    #pragma unroll 1
    for (int i = 0; i < 25; i++) {
        int o = oc * 200 + w * 25 + i;
        const float* row;
        if (o < NH) row = Wa + o * NH;
        else        row = Whh + (o - NH) * NH;
        float s = 0.f;
        #pragma unroll
        for (int k = l; k < NH; k += 32) s = fmaf(hs[k], row[k], s);
        s = warp_sum(s);
        if (l == 0) {
            if (o < NH) g_qproj[b * NH + o] = s + ba[o];
            else        g_hpre[b * NH4 + (o - NH)] = s + bhh[o - NH];
        }
    }
}

// ============================================================================
// K2: scores, bf16 mma.sync, persistent 148 CTAs, 512 threads (R4 structure).
//   Inner kt pipeline rebuilt: B fragments via ldmatrix.x4 (2 kt per load)
//   through a 3-deep ring buffer -> prefetch distance 3 pairs, so MMAs never
//   wait on LDS-latency operands.  Even/odd kt accumulator chains retained.
// ============================================================================
#define NCTA 148
#define MT 64
#define NP 224
#define ASTR 216
#define AW 108
#define BS_U32 (NP * AW)
#define AS_U32 (MT * AW)
#define NTILES (NB * 32)
#define SMEM_SC ((BS_U32 + 2 * AS_U32) * 4 + 2 * NP * 8 + 4 * 64 * 4 + 16)

__device__ __forceinline__ void stage_tile(
    uint32_t* __restrict__ dst, float2* __restrict__ vqd,
    const float* __restrict__ enc, const float* __restrict__ Va,
    const float* __restrict__ bua, int b, int trow, int tid) {
    const float* eb = enc + ((size_t)b * NT + trow) * NH;
    #pragma unroll 1
    for (int i = tid; i < MT * AW; i += 512) {
        int r = i / AW, p = i - r * AW;
        uint32_t v = 0;
        if (p < 100) {
            float2 f = *(const float2*)(eb + r * NH + 2 * p);
            v = pack_bf2(f.x, f.y);
        }
        dst[r * AW + p] = v;
    }
    if (tid < NP) {
        float vv = 0.f, qq = 0.f;
        if (tid < NH) { vv = Va[tid]; qq = g_qproj[b * NH + tid] + bua[tid]; }
        vqd[tid] = make_float2(vv, qq);
    }
}

__global__ __launch_bounds__(512, 1) void k_scores(
    const float* __restrict__ enc, const float* __restrict__ Ua,
    const float* __restrict__ bua, const float* __restrict__ Va,
    const float* __restrict__ bva) {
    extern __shared__ uint32_t sm32[];
    uint32_t* Bs  = sm32;
    uint32_t* As0 = Bs + BS_U32;
    uint32_t* As1 = As0 + AS_U32;
    float2*   vq  = (float2*)(As1 + AS_U32);
    float*    srow = (float*)(vq + 2 * NP);

    const int tid = threadIdx.x, l = tid & 31, wid = tid >> 5;
    const int mw = wid & 3, nw = wid >> 2;
    const int bid = blockIdx.x;
    const float bv0 = bva[0];
    const int njt = (nw == 0) ? 7 : 6;
    const int ncol = nw ? (8 + nw * 48) : 0;      // 0,56,104,152

    for (int i = tid; i < BS_U32; i += 512) Bs[i] = 0;
    __syncthreads();
    for (int i = tid; i < NH * 100; i += 512) {
        int n = i / 100, k2 = i - n * 100;
        float2 f = *(const float2*)(Ua + n * NH + 2 * k2);
        Bs[n * AW + k2] = pack_bf2(f.x, f.y);
    }

    const int ntile = (NTILES - bid + NCTA - 1) / NCTA;
    {
        int gt = bid;
        stage_tile(As0, vq, enc, Va, bua, gt >> 5, (gt & 31) << 6, tid);
    }
    __syncthreads();

    // x4 B base: lane groups of 8 -> k offsets 0,8,16,24 (two kt per load)
    const uint32_t bbase4 = s2u(Bs) + ((ncol + (l & 7)) * ASTR + (l >> 3) * 8) * 2;
    // x2 tail base for kt=12 (k 192..207)
    const uint32_t bbase2 = s2u(Bs) + ((ncol + (l & 7)) * ASTR + ((l >> 3) & 1) * 8 + 192) * 2;

    #pragma unroll 1
    for (int it = 0; it < ntile; it++) {
        const int cur = it & 1;
        uint32_t* Ac = cur ? As1 : As0;

        uint32_t a[13][4];
        {
            uint32_t abase = s2u(Ac) + ((mw * 16 + (l & 15)) * ASTR + (l >> 4) * 8) * 2;
            #pragma unroll
            for (int kt = 0; kt < 13; kt++)
                asm volatile("ldmatrix.sync.aligned.m8n8.x4.shared.b16 {%0,%1,%2,%3}, [%4];"
                    : "=r"(a[kt][0]), "=r"(a[kt][1]), "=r"(a[kt][2]), "=r"(a[kt][3])
                    : "r"(abase + kt * 32));
        }

        if (it + 1 < ntile) {
            int gtn = bid + (it + 1) * NCTA;
            stage_tile(cur ? As0 : As1, vq + (1 - cur) * NP,
                       enc, Va, bua, gtn >> 5, (gtn & 31) << 6, tid);
        }

        float slo = 0.f, shi = 0.f;
        const float2* vql = vq + cur * NP;
        #pragma unroll 1
        for (int jt = 0; jt < njt; jt++) {
            const uint32_t bb = bbase4 + (uint32_t)(jt * 8 * ASTR * 2);
            uint32_t bf[3][4];     // ring: 3 kt-pairs in flight
            uint32_t e0, e1;       // kt=12 tail
            #pragma unroll
            for (int p = 0; p < 3; p++)
                asm volatile("ldmatrix.sync.aligned.m8n8.x4.shared.b16 {%0,%1,%2,%3}, [%4];"
                    : "=r"(bf[p][0]), "=r"(bf[p][1]), "=r"(bf[p][2]), "=r"(bf[p][3])
                    : "r"(bb + p * 64));
            asm volatile("ldmatrix.sync.aligned.m8n8.x2.shared.b16 {%0,%1}, [%2];"
                : "=r"(e0), "=r"(e1) : "r"(bbase2 + (uint32_t)(jt * 8 * ASTR * 2)));

            float c0 = 0.f, c1 = 0.f, c2 = 0.f, c3 = 0.f;   // even kt chain
            float d0 = 0.f, d1 = 0.f, d2 = 0.f, d3 = 0.f;   // odd kt chain
            #pragma unroll
            for (int p = 0; p < 6; p++) {
                const int slot = p % 3;
                uint32_t r0 = bf[slot][0], r1 = bf[slot][1];
                uint32_t r2 = bf[slot][2], r3 = bf[slot][3];
                if (p < 3)   // prefetch pair p+3 (distance-3: latency covered)
                    asm volatile("ldmatrix.sync.aligned.m8n8.x4.shared.b16 {%0,%1,%2,%3}, [%4];"
                        : "=r"(bf[slot][0]), "=r"(bf[slot][1]),
                          "=r"(bf[slot][2]), "=r"(bf[slot][3])
                        : "r"(bb + (p + 3) * 64));
                asm volatile("mma.sync.aligned.m16n8k16.row.col.f32.bf16.bf16.f32 "
                    "{%0,%1,%2,%3},{%4,%5,%6,%7},{%8,%9},{%0,%1,%2,%3};"
                    : "+f"(c0), "+f"(c1), "+f"(c2), "+f"(c3)
                    : "r"(a[2*p][0]), "r"(a[2*p][1]), "r"(a[2*p][2]), "r"(a[2*p][3]),
                      "r"(r0), "r"(r1));
                asm volatile("mma.sync.aligned.m16n8k16.row.col.f32.bf16.bf16.f32 "
                    "{%0,%1,%2,%3},{%4,%5,%6,%7},{%8,%9},{%0,%1,%2,%3};"
                    : "+f"(d0), "+f"(d1), "+f"(d2), "+f"(d3)
                    : "r"(a[2*p+1][0]), "r"(a[2*p+1][1]), "r"(a[2*p+1][2]), "r"(a[2*p+1][3]),
                      "r"(r2), "r"(r3));
            }
            asm volatile("mma.sync.aligned.m16n8k16.row.col.f32.bf16.bf16.f32 "
                "{%0,%1,%2,%3},{%4,%5,%6,%7},{%8,%9},{%0,%1,%2,%3};"
                : "+f"(c0), "+f"(c1), "+f"(c2), "+f"(c3)
                : "r"(a[12][0]), "r"(a[12][1]), "r"(a[12][2]), "r"(a[12][3]),
                  "r"(e0), "r"(e1));

            c0 += d0; c1 += d1; c2 += d2; c3 += d3;
            const int j0 = ncol + jt * 8 + 2 * (l & 3);
            const float2 v0 = vql[j0], v1 = vql[j0 + 1];
            slo = fmaf(v0.x, tanh_mufu(c0 + v0.y), slo);
            slo = fmaf(v1.x, tanh_mufu(c1 + v1.y), slo);
            shi = fmaf(v0.x, tanh_mufu(c2 + v0.y), shi);
            shi = fmaf(v1.x, tanh_mufu(c3 + v1.y), shi);
        }
        slo += __shfl_xor_sync(0xffffffffu, slo, 1);
        slo += __shfl_xor_sync(0xffffffffu, slo, 2);
        shi += __shfl_xor_sync(0xffffffffu, shi, 1);
        shi += __shfl_xor_sync(0xffffffffu, shi, 2);
        if ((l & 3) == 0) {
            srow[nw * 64 + mw * 16 + (l >> 2)] = slo;
            srow[nw * 64 + mw * 16 + (l >> 2) + 8] = shi;
        }
        __syncthreads();

        const int gt = bid + it * NCTA;
        if (tid < 64) {
            g_scores[(size_t)(gt >> 5) * NT + ((gt & 31) << 6) + tid] =
                srow[tid] + srow[64 + tid] + srow[128 + tid] + srow[192 + tid] + bv0;
        }
        __syncthreads();
    }
}

// ============================================================================
// K3: softmax over T + context.
// ============================================================================
__global__ __launch_bounds__(1024) void k_softctx(const float* __restrict__ enc) {
    const int b = blockIdx.x, tid = threadIdx.x;
    __shared__ float at[NT];
    __shared__ float red[1024];
    __shared__ float part[4][NH];

    float m = -1e30f;
    #pragma unroll
    for (int t = tid; t < NT; t += 1024) {
        float s = g_scores[(size_t)b * NT + t];
        at[t] = s;
        m = fmaxf(m, s);
    }
    red[tid] = m; __syncthreads();
    for (int o = 512; o; o >>= 1) {
        if (tid < o) red[tid] = fmaxf(red[tid], red[tid + o]);
        __syncthreads();
    }
    m = red[0]; __syncthreads();

    float lsum = 0.f;
    #pragma unroll
    for (int t = tid; t < NT; t += 1024) {
        float e = expf(at[t] - m);
        at[t] = e;
        lsum += e;
    }
    red[tid] = lsum; __syncthreads();
    for (int o = 512; o; o >>= 1) {
        if (tid < o) red[tid] += red[tid + o];
        __syncthreads();
    }
    const float inv = 1.f / red[0];
    __syncthreads();

    const int p = tid >> 8, hh = tid & 255;
    if (hh < NH) {
        const float* e = enc + (size_t)b * NT * NH + (size_t)p * 512 * NH + hh;
        const float* atp = at + p * 512;
        float a = 0.f;
        #pragma unroll 8
        for (int t = 0; t < 512; t++) a = fmaf(atp[t], e[(size_t)t * NH], a);
        part[p][hh] = a;
    }
    __syncthreads();
    if (tid < NH)
        g_context[b * NH + tid] =
            (part[0][tid] + part[1][tid] + part[2][tid] + part[3][tid]) * inv;
}

// ============================================================================
// K4: gates_const[b,j] = b_ih[j] + h_pre[b,j] + ctx . W_ih[j,1:]   grid(4,NB)
// ============================================================================
__global__ void k_gates(const float* __restrict__ Wih, const float* __restrict__ bih) {
    const int b = blockIdx.y, jc = blockIdx.x, tid = threadIdx.x;
    const int w = tid >> 5, l = tid & 31;
    __shared__ float ctx[NH];
    if (tid < NH) ctx[tid] = g_context[b * NH + tid];
    __syncthreads();
    #pragma unroll 1
    for (int i = 0; i < 25; i++) {
        int j = jc * 200 + w * 25 + i;
        const float* row = Wih + (size_t)j * (NH + 1) + 1;
        float s = 0.f;
        #pragma unroll
        for (int k = l; k < NH; k += 32) s = fmaf(ctx[k], row[k], s);
        s = warp_sum(s);
        if (l == 0) g_gc[b * NH4 + j] = s + bih[j] + g_hpre[b * NH4 + j];
    }
}

// ============================================================================
// K5: 5-step decode.
// ============================================================================
#define SMEM_DEC ((20000 + 5000 + 64 + 128 + 64 + NH4 + NH4 + NH + NH + 128 + 64 + 8) * 4)
__global__ __launch_bounds__(256) void k_decode(
    const float* __restrict__ x_in, const float* __restrict__ c0,
    const float* __restrict__ Wih,
    const float* __restrict__ W1, const float* __restrict__ b1,
    const float* __restrict__ W2, const float* __restrict__ b2,
    const float* __restrict__ W3, const float* __restrict__ b3,
    float* __restrict__ out) {
    extern __shared__ float sd[];
    float* W1s = sd;
    float* W2s = W1s + 20000;
    float* W3s = W2s + 5000;
    float* b1s = W3s + 64;
    float* b2s = b1s + 128;
    float* gc  = b2s + 64;
    float* w0  = gc + NH4;
    float* c0s = w0 + NH4;
    float* buf0 = c0s + NH;
    float* buf1 = buf0 + NH;
    float* buf2 = buf1 + 128;
    float* xcur = buf2 + 64;

    const int b = blockIdx.x, tid = threadIdx.x;
    const int w = tid >> 5, l = tid & 31;

    for (int i = tid; i < 20000; i += 256) W1s[i] = W1[i];
    for (int i = tid; i < 5000; i += 256) W2s[i] = W2[i];
    if (tid < 50) { W3s[tid] = W3[tid]; b2s[tid] = b2[tid]; }
    if (tid < 100) b1s[tid] = b1[tid];
    for (int i = tid; i < NH4; i += 256) {
        gc[i] = g_gc[b * NH4 + i];
        w0[i] = Wih[(size_t)i * (NH + 1)];
    }
    if (tid < NH) c0s[tid] = c0[b * NH + tid];
    if (tid == 0) xcur[0] = x_in[b];
    __syncthreads();

    const float b3v = b3[0];
    for (int st = 0; st < NSTEP; st++) {
        const float xv = xcur[0];
        if (tid < NH) {
            float gi = fmaf(xv, w0[tid], gc[tid]);
            float gf = fmaf(xv, w0[NH + tid], gc[NH + tid]);
            float gg = fmaf(xv, w0[2 * NH + tid], gc[2 * NH + tid]);
            float go = fmaf(xv, w0[3 * NH + tid], gc[3 * NH + tid]);
            float c  = sigm(gf) * c0s[tid] + sigm(gi) * tanhf(gg);
            buf0[tid] = fmaxf(sigm(go) * tanhf(c), 0.f);
        }
        __syncthreads();
        #pragma unroll 1
        for (int i = 0; i < 13; i++) {
            int j = w + 8 * i; int jj = min(j, 99);
            float s = 0.f;
            #pragma unroll
            for (int k = l; k < NH; k += 32) s = fmaf(W1s[jj * NH + k], buf0[k], s);
            s = warp_sum(s);
            if (l == 0 && j < 100) buf1[j] = fmaxf(s + b1s[j], 0.f);
        }
        __syncthreads();
        #pragma unroll 1
        for (int i = 0; i < 7; i++) {
            int j = w + 8 * i; int jj = min(j, 49);
            float s = 0.f;
            #pragma unroll
            for (int k = l; k < 100; k += 32) s = fmaf(W2s[jj * 100 + k], buf1[k], s);
            s = warp_sum(s);
            if (l == 0 && j < 50) buf2[j] = fmaxf(s + b2s[j], 0.f);
        }
        __syncthreads();
        if (w == 0) {
            float s = (l < 50) ? W3s[l] * buf2[l] : 0.f;
            if (l < 18) s = fmaf(W3s[l + 32], buf2[l + 32], s);
            s = warp_sum(s);
            if (l == 0) {
                float y = s + b3v;
                out[b * NSTEP + st] = y;
                xcur[0] = y;
            }
        }
        __syncthreads();
    }
}

// ============================================================================
extern "C" void kernel_launch(void* const* d_in, const int* in_sizes, int n_in,
                              void* d_out, int out_size) {
    const float* x   = (const float*)d_in[0];
    const float* h0  = (const float*)d_in[1];
    const float* c0  = (const float*)d_in[2];
    const float* enc = (const float*)d_in[3];
    const float* Wa  = (const float*)d_in[4];
    const float* ba  = (const float*)d_in[5];
    const float* Ua  = (const float*)d_in[6];
    const float* bua = (const float*)d_in[7];
    const float* Va  = (const float*)d_in[8];
    const float* bva = (const float*)d_in[9];
    const float* Wih = (const float*)d_in[10];
    const float* Whh = (const float*)d_in[11];
    const float* bih = (const float*)d_in[12];
    const float* bhh = (const float*)d_in[13];
    const float* W1  = (const float*)d_in[14];
    const float* b1  = (const float*)d_in[15];
    const float* W2  = (const float*)d_in[16];
    const float* b2  = (const float*)d_in[17];
    const float* W3  = (const float*)d_in[18];
    const float* b3  = (const float*)d_in[19];
    float* out = (float*)d_out;

    cudaFuncSetAttribute(k_scores, cudaFuncAttributeMaxDynamicSharedMemorySize,
                         (int)SMEM_SC);
    cudaFuncSetAttribute(k_decode, cudaFuncAttributeMaxDynamicSharedMemorySize,
                         (int)SMEM_DEC);

    k_pre<<<dim3(5, NB), 256>>>(h0, Wa, ba, Whh, bhh);
    k_nop<<<1, 32>>>();
    k_nop<<<1, 32>>>();
    k_scores<<<NCTA, 512, SMEM_SC>>>(enc, Ua, bua, Va, bva);   // profiled slot
    k_softctx<<<NB, 1024>>>(enc);
    k_gates<<<dim3(4, NB), 256>>>(Wih, bih);
    k_decode<<<NB, 256, SMEM_DEC>>>(x, c0, Wih, W1, b1, W2, b2, W3, b3, out);
}

// round 8
// speedup vs baseline: 3.8395x; 1.5485x over previous
#include <cuda_runtime.h>
#include <cuda_bf16.h>
#include <math.h>
#include <stdint.h>

#define NB 128
#define NT 2048
#define NH 200
#define NH4 800
#define NSTEP 5

// ---- scratch ----
__device__ float g_qproj[NB * NH];
__device__ float g_hpre[NB * NH4];
__device__ float g_scores[NB * NT];
__device__ float g_context[NB * NH];
__device__ float g_gc[NB * NH4];

__device__ __forceinline__ float sigm(float x) { return 1.f / (1.f + expf(-x)); }

__device__ __forceinline__ float tanh_mufu(float x) {
    float m = x * 2.8853900817779268f;   // 2*log2(e)
    float e; asm("ex2.approx.ftz.f32 %0, %1;" : "=f"(e) : "f"(m));
    float d = 1.f + e;
    float rc; asm("rcp.approx.ftz.f32 %0, %1;" : "=f"(rc) : "f"(d));
    return fmaf(-2.f, rc, 1.f);
}

__device__ __forceinline__ uint32_t pack_bf2(float lo, float hi) {
    uint32_t r;
    asm("cvt.rn.bf16x2.f32 %0, %1, %2;" : "=r"(r) : "f"(hi), "f"(lo));
    return r;
}
__device__ __forceinline__ float warp_sum(float s) {
    #pragma unroll
    for (int o = 16; o; o >>= 1) s += __shfl_xor_sync(0xffffffffu, s, o);
    return s;
}
__device__ __forceinline__ uint32_t s2u(const void* p) {
    return (uint32_t)__cvta_generic_to_shared(p);
}

// no-op kernel: keeps ncu's captured launch index on k_scores
__global__ void k_nop() {}

// ============================================================================
// K1: warp-per-output gemv: q_proj (Wa) + h_pre (W_hh).  grid(5, NB)
// ============================================================================
__global__ void k_pre(const float* __restrict__ h0, const float* __restrict__ Wa,
                      const float* __restrict__ ba, const float* __restrict__ Whh,
                      const float* __restrict__ bhh) {
    const int b = blockIdx.y, oc = blockIdx.x, tid = threadIdx.x;
    const int w = tid >> 5, l = tid & 31;
    __shared__ float hs[NH];
    if (tid < NH) hs[tid] = h0[b * NH + tid];
    __syncthreads();
    #pragma unroll 1
    for (int i = 0; i < 25; i++) {
        int o = oc * 200 + w * 25 + i;
        const float* row;
        if (o < NH) row = Wa + o * NH;
        else        row = Whh + (o - NH) * NH;
        float s = 0.f;
        #pragma unroll
        for (int k = l; k < NH; k += 32) s = fmaf(hs[k], row[k], s);
        s = warp_sum(s);
        if (l == 0) {
            if (o < NH) g_qproj[b * NH + o] = s + ba[o];
            else        g_hpre[b * NH4 + (o - NH)] = s + bhh[o - NH];
        }
    }
}

// ============================================================================
// K2: scores, bf16 mma.sync, persistent 148 CTAs, 512 threads.
//   Staging rebuilt: batch-load phase (14 LDG.64 in flight, MLP=14) then
//   batch convert+STS phase -- kills the serial LDG->STS chain that was
//   costing ~8.4k cyc/tile.  Ring-buffered B prefetch (R7) retained.
// ============================================================================
#define NCTA 148
#define MT 64
#define NP 224
#define ASTR 216
#define AW 108
#define BS_U32 (NP * AW)
#define AS_U32 (MT * AW)
#define NTILES (NB * 32)
#define SMEM_SC ((BS_U32 + 2 * AS_U32) * 4 + 2 * NP * 8 + 4 * 64 * 4 + 16)

__device__ __forceinline__ void stage_tile(
    uint32_t* __restrict__ dst, float2* __restrict__ vqd,
    const float* __restrict__ enc, const float* __restrict__ Va,
    const float* __restrict__ bua, int b, int trow, int tid) {
    const float* eb = enc + ((size_t)b * NT + trow) * NH;
    // phase 1: all loads in flight (no dependent stores between them)
    float2 f[14];
    #pragma unroll
    for (int i = 0; i < 14; i++) {
        int idx = tid + (i << 9);
        int r = idx / AW, p = idx - r * AW;
        bool ok = (i < 13 || tid < 256) && (p < 100);
        f[i] = make_float2(0.f, 0.f);
        if (ok) f[i] = *(const float2*)(eb + r * NH + 2 * p);
    }
    // phase 2: convert + store
    #pragma unroll
    for (int i = 0; i < 14; i++) {
        int idx = tid + (i << 9);
        if (i < 13 || tid < 256) dst[idx] = pack_bf2(f[i].x, f[i].y);
    }
    if (tid < NP) {
        float vv = 0.f, qq = 0.f;
        if (tid < NH) { vv = Va[tid]; qq = g_qproj[b * NH + tid] + bua[tid]; }
        vqd[tid] = make_float2(vv, qq);
    }
}

__global__ __launch_bounds__(512, 1) void k_scores(
    const float* __restrict__ enc, const float* __restrict__ Ua,
    const float* __restrict__ bua, const float* __restrict__ Va,
    const float* __restrict__ bva) {
    extern __shared__ uint32_t sm32[];
    uint32_t* Bs  = sm32;
    uint32_t* As0 = Bs + BS_U32;
    uint32_t* As1 = As0 + AS_U32;
    float2*   vq  = (float2*)(As1 + AS_U32);
    float*    srow = (float*)(vq + 2 * NP);

    const int tid = threadIdx.x, l = tid & 31, wid = tid >> 5;
    const int mw = wid & 3, nw = wid >> 2;
    const int bid = blockIdx.x;
    const float bv0 = bva[0];
    const int njt = (nw == 0) ? 7 : 6;
    const int ncol = nw ? (8 + nw * 48) : 0;      // 0,56,104,152

    for (int i = tid; i < BS_U32; i += 512) Bs[i] = 0;
    __syncthreads();
    for (int i = tid; i < NH * 100; i += 512) {
        int n = i / 100, k2 = i - n * 100;
        float2 f = *(const float2*)(Ua + n * NH + 2 * k2);
        Bs[n * AW + k2] = pack_bf2(f.x, f.y);
    }

    const int ntile = (NTILES - bid + NCTA - 1) / NCTA;
    {
        int gt = bid;
        stage_tile(As0, vq, enc, Va, bua, gt >> 5, (gt & 31) << 6, tid);
    }
    __syncthreads();

    const uint32_t bbase4 = s2u(Bs) + ((ncol + (l & 7)) * ASTR + (l >> 3) * 8) * 2;
    const uint32_t bbase2 = s2u(Bs) + ((ncol + (l & 7)) * ASTR + ((l >> 3) & 1) * 8 + 192) * 2;

    #pragma unroll 1
    for (int it = 0; it < ntile; it++) {
        const int cur = it & 1;
        uint32_t* Ac = cur ? As1 : As0;

        // stage next tile FIRST (batched loads; latency absorbed once)
        if (it + 1 < ntile) {
            int gtn = bid + (it + 1) * NCTA;
            stage_tile(cur ? As0 : As1, vq + (1 - cur) * NP,
                       enc, Va, bua, gtn >> 5, (gtn & 31) << 6, tid);
        }

        uint32_t a[13][4];
        {
            uint32_t abase = s2u(Ac) + ((mw * 16 + (l & 15)) * ASTR + (l >> 4) * 8) * 2;
            #pragma unroll
            for (int kt = 0; kt < 13; kt++)
                asm volatile("ldmatrix.sync.aligned.m8n8.x4.shared.b16 {%0,%1,%2,%3}, [%4];"
                    : "=r"(a[kt][0]), "=r"(a[kt][1]), "=r"(a[kt][2]), "=r"(a[kt][3])
                    : "r"(abase + kt * 32));
        }

        float slo = 0.f, shi = 0.f;
        const float2* vql = vq + cur * NP;
        #pragma unroll 1
        for (int jt = 0; jt < njt; jt++) {
            const uint32_t bb = bbase4 + (uint32_t)(jt * 8 * ASTR * 2);
            uint32_t bf[3][4];     // ring: 3 kt-pairs in flight
            uint32_t e0, e1;       // kt=12 tail
            #pragma unroll
            for (int p = 0; p < 3; p++)
                asm volatile("ldmatrix.sync.aligned.m8n8.x4.shared.b16 {%0,%1,%2,%3}, [%4];"
                    : "=r"(bf[p][0]), "=r"(bf[p][1]), "=r"(bf[p][2]), "=r"(bf[p][3])
                    : "r"(bb + p * 64));
            asm volatile("ldmatrix.sync.aligned.m8n8.x2.shared.b16 {%0,%1}, [%2];"
                : "=r"(e0), "=r"(e1) : "r"(bbase2 + (uint32_t)(jt * 8 * ASTR * 2)));

            float c0 = 0.f, c1 = 0.f, c2 = 0.f, c3 = 0.f;
            float d0 = 0.f, d1 = 0.f, d2 = 0.f, d3 = 0.f;
            #pragma unroll
            for (int p = 0; p < 6; p++) {
                const int slot = p % 3;
                uint32_t r0 = bf[slot][0], r1 = bf[slot][1];
                uint32_t r2 = bf[slot][2], r3 = bf[slot][3];
                if (p < 3)
                    asm volatile("ldmatrix.sync.aligned.m8n8.x4.shared.b16 {%0,%1,%2,%3}, [%4];"
                        : "=r"(bf[slot][0]), "=r"(bf[slot][1]),
                          "=r"(bf[slot][2]), "=r"(bf[slot][3])
                        : "r"(bb + (p + 3) * 64));
                asm volatile("mma.sync.aligned.m16n8k16.row.col.f32.bf16.bf16.f32 "
                    "{%0,%1,%2,%3},{%4,%5,%6,%7},{%8,%9},{%0,%1,%2,%3};"
                    : "+f"(c0), "+f"(c1), "+f"(c2), "+f"(c3)
                    : "r"(a[2*p][0]), "r"(a[2*p][1]), "r"(a[2*p][2]), "r"(a[2*p][3]),
                      "r"(r0), "r"(r1));
                asm volatile("mma.sync.aligned.m16n8k16.row.col.f32.bf16.bf16.f32 "
                    "{%0,%1,%2,%3},{%4,%5,%6,%7},{%8,%9},{%0,%1,%2,%3};"
                    : "+f"(d0), "+f"(d1), "+f"(d2), "+f"(d3)
                    : "r"(a[2*p+1][0]), "r"(a[2*p+1][1]), "r"(a[2*p+1][2]), "r"(a[2*p+1][3]),
                      "r"(r2), "r"(r3));
            }
            asm volatile("mma.sync.aligned.m16n8k16.row.col.f32.bf16.bf16.f32 "
                "{%0,%1,%2,%3},{%4,%5,%6,%7},{%8,%9},{%0,%1,%2,%3};"
                : "+f"(c0), "+f"(c1), "+f"(c2), "+f"(c3)
                : "r"(a[12][0]), "r"(a[12][1]), "r"(a[12][2]), "r"(a[12][3]),
                  "r"(e0), "r"(e1));

            c0 += d0; c1 += d1; c2 += d2; c3 += d3;
            const int j0 = ncol + jt * 8 + 2 * (l & 3);
            const float2 v0 = vql[j0], v1 = vql[j0 + 1];
            slo = fmaf(v0.x, tanh_mufu(c0 + v0.y), slo);
            slo = fmaf(v1.x, tanh_mufu(c1 + v1.y), slo);
            shi = fmaf(v0.x, tanh_mufu(c2 + v0.y), shi);
            shi = fmaf(v1.x, tanh_mufu(c3 + v1.y), shi);
        }
        slo += __shfl_xor_sync(0xffffffffu, slo, 1);
        slo += __shfl_xor_sync(0xffffffffu, slo, 2);
        shi += __shfl_xor_sync(0xffffffffu, shi, 1);
        shi += __shfl_xor_sync(0xffffffffu, shi, 2);
        if ((l & 3) == 0) {
            srow[nw * 64 + mw * 16 + (l >> 2)] = slo;
            srow[nw * 64 + mw * 16 + (l >> 2) + 8] = shi;
        }
        __syncthreads();

        const int gt = bid + it * NCTA;
        if (tid < 64) {
            g_scores[(size_t)(gt >> 5) * NT + ((gt & 31) << 6) + tid] =
                srow[tid] + srow[64 + tid] + srow[128 + tid] + srow[192 + tid] + bv0;
        }
        __syncthreads();
    }
}

// ============================================================================
// K3: softmax over T + context.
// ============================================================================
__global__ __launch_bounds__(1024) void k_softctx(const float* __restrict__ enc) {
    const int b = blockIdx.x, tid = threadIdx.x;
    __shared__ float at[NT];
    __shared__ float red[1024];
    __shared__ float part[4][NH];

    float m = -1e30f;
    #pragma unroll
    for (int t = tid; t < NT; t += 1024) {
        float s = g_scores[(size_t)b * NT + t];
        at[t] = s;
        m = fmaxf(m, s);
    }
    red[tid] = m; __syncthreads();
    for (int o = 512; o; o >>= 1) {
        if (tid < o) red[tid] = fmaxf(red[tid], red[tid + o]);
        __syncthreads();
    }
    m = red[0]; __syncthreads();

    float lsum = 0.f;
    #pragma unroll
    for (int t = tid; t < NT; t += 1024) {
        float e = expf(at[t] - m);
        at[t] = e;
        lsum += e;
    }
    red[tid] = lsum; __syncthreads();
    for (int o = 512; o; o >>= 1) {
        if (tid < o) red[tid] += red[tid + o];
        __syncthreads();
    }
    const float inv = 1.f / red[0];
    __syncthreads();

    const int p = tid >> 8, hh = tid & 255;
    if (hh < NH) {
        const float* e = enc + (size_t)b * NT * NH + (size_t)p * 512 * NH + hh;
        const float* atp = at + p * 512;
        float a = 0.f;
        #pragma unroll 8
        for (int t = 0; t < 512; t++) a = fmaf(atp[t], e[(size_t)t * NH], a);
        part[p][hh] = a;
    }
    __syncthreads();
    if (tid < NH)
        g_context[b * NH + tid] =
            (part[0][tid] + part[1][tid] + part[2][tid] + part[3][tid]) * inv;
}

// ============================================================================
// K4: gates_const[b,j] = b_ih[j] + h_pre[b,j] + ctx . W_ih[j,1:]   grid(4,NB)
// ============================================================================
__global__ void k_gates(const float* __restrict__ Wih, const float* __restrict__ bih) {
    const int b = blockIdx.y, jc = blockIdx.x, tid = threadIdx.x;
    const int w = tid >> 5, l = tid & 31;
    __shared__ float ctx[NH];
    if (tid < NH) ctx[tid] = g_context[b * NH + tid];
    __syncthreads();
    #pragma unroll 1
    for (int i = 0; i < 25; i++) {
        int j = jc * 200 + w * 25 + i;
        const float* row = Wih + (size_t)j * (NH + 1) + 1;
        float s = 0.f;
        #pragma unroll
        for (int k = l; k < NH; k += 32) s = fmaf(ctx[k], row[k], s);
        s = warp_sum(s);
        if (l == 0) g_gc[b * NH4 + j] = s + bih[j] + g_hpre[b * NH4 + j];
    }
}

// ============================================================================
// K5: 5-step decode.
// ============================================================================
#define SMEM_DEC ((20000 + 5000 + 64 + 128 + 64 + NH4 + NH4 + NH + NH + 128 + 64 + 8) * 4)
__global__ __launch_bounds__(256) void k_decode(
    const float* __restrict__ x_in, const float* __restrict__ c0,
    const float* __restrict__ Wih,
    const float* __restrict__ W1, const float* __restrict__ b1,
    const float* __restrict__ W2, const float* __restrict__ b2,
    const float* __restrict__ W3, const float* __restrict__ b3,
    float* __restrict__ out) {
    extern __shared__ float sd[];
    float* W1s = sd;
    float* W2s = W1s + 20000;
    float* W3s = W2s + 5000;
    float* b1s = W3s + 64;
    float* b2s = b1s + 128;
    float* gc  = b2s + 64;
    float* w0  = gc + NH4;
    float* c0s = w0 + NH4;
    float* buf0 = c0s + NH;
    float* buf1 = buf0 + NH;
    float* buf2 = buf1 + 128;
    float* xcur = buf2 + 64;

    const int b = blockIdx.x, tid = threadIdx.x;
    const int w = tid >> 5, l = tid & 31;

    for (int i = tid; i < 20000; i += 256) W1s[i] = W1[i];
    for (int i = tid; i < 5000; i += 256) W2s[i] = W2[i];
    if (tid < 50) { W3s[tid] = W3[tid]; b2s[tid] = b2[tid]; }
    if (tid < 100) b1s[tid] = b1[tid];
    for (int i = tid; i < NH4; i += 256) {
        gc[i] = g_gc[b * NH4 + i];
        w0[i] = Wih[(size_t)i * (NH + 1)];
    }
    if (tid < NH) c0s[tid] = c0[b * NH + tid];
    if (tid == 0) xcur[0] = x_in[b];
    __syncthreads();

    const float b3v = b3[0];
    for (int st = 0; st < NSTEP; st++) {
        const float xv = xcur[0];
        if (tid < NH) {
            float gi = fmaf(xv, w0[tid], gc[tid]);
            float gf = fmaf(xv, w0[NH + tid], gc[NH + tid]);
            float gg = fmaf(xv, w0[2 * NH + tid], gc[2 * NH + tid]);
            float go = fmaf(xv, w0[3 * NH + tid], gc[3 * NH + tid]);
            float c  = sigm(gf) * c0s[tid] + sigm(gi) * tanhf(gg);
            buf0[tid] = fmaxf(sigm(go) * tanhf(c), 0.f);
        }
        __syncthreads();
        #pragma unroll 1
        for (int i = 0; i < 13; i++) {
            int j = w + 8 * i; int jj = min(j, 99);
            float s = 0.f;
            #pragma unroll
            for (int k = l; k < NH; k += 32) s = fmaf(W1s[jj * NH + k], buf0[k], s);
            s = warp_sum(s);
            if (l == 0 && j < 100) buf1[j] = fmaxf(s + b1s[j], 0.f);
        }
        __syncthreads();
        #pragma unroll 1
        for (int i = 0; i < 7; i++) {
            int j = w + 8 * i; int jj = min(j, 49);
            float s = 0.f;
            #pragma unroll
            for (int k = l; k < 100; k += 32) s = fmaf(W2s[jj * 100 + k], buf1[k], s);
            s = warp_sum(s);
            if (l == 0 && j < 50) buf2[j] = fmaxf(s + b2s[j], 0.f);
        }
        __syncthreads();
        if (w == 0) {
            float s = (l < 50) ? W3s[l] * buf2[l] : 0.f;
            if (l < 18) s = fmaf(W3s[l + 32], buf2[l + 32], s);
            s = warp_sum(s);
            if (l == 0) {
                float y = s + b3v;
                out[b * NSTEP + st] = y;
                xcur[0] = y;
            }
        }
        __syncthreads();
    }
}

// ============================================================================
extern "C" void kernel_launch(void* const* d_in, const int* in_sizes, int n_in,
                              void* d_out, int out_size) {
    const float* x   = (const float*)d_in[0];
    const float* h0  = (const float*)d_in[1];
    const float* c0  = (const float*)d_in[2];
    const float* enc = (const float*)d_in[3];
    const float* Wa  = (const float*)d_in[4];
    const float* ba  = (const float*)d_in[5];
    const float* Ua  = (const float*)d_in[6];
    const float* bua = (const float*)d_in[7];
    const float* Va  = (const float*)d_in[8];
    const float* bva = (const float*)d_in[9];
    const float* Wih = (const float*)d_in[10];
    const float* Whh = (const float*)d_in[11];
    const float* bih = (const float*)d_in[12];
    const float* bhh = (const float*)d_in[13];
    const float* W1  = (const float*)d_in[14];
    const float* b1  = (const float*)d_in[15];
    const float* W2  = (const float*)d_in[16];
    const float* b2  = (const float*)d_in[17];
    const float* W3  = (const float*)d_in[18];
    const float* b3  = (const float*)d_in[19];
    float* out = (float*)d_out;

    cudaFuncSetAttribute(k_scores, cudaFuncAttributeMaxDynamicSharedMemorySize,
                         (int)SMEM_SC);
    cudaFuncSetAttribute(k_decode, cudaFuncAttributeMaxDynamicSharedMemorySize,
                         (int)SMEM_DEC);

    k_pre<<<dim3(5, NB), 256>>>(h0, Wa, ba, Whh, bhh);
    k_nop<<<1, 32>>>();
    k_nop<<<1, 32>>>();
    k_scores<<<NCTA, 512, SMEM_SC>>>(enc, Ua, bua, Va, bva);   // profiled slot
    k_softctx<<<NB, 1024>>>(enc);
    k_gates<<<dim3(4, NB), 256>>>(Wih, bih);
    k_decode<<<NB, 256, SMEM_DEC>>>(x, c0, Wih, W1, b1, W2, b2, W3, b3, out);
}